// round 14
// baseline (speedup 1.0000x reference)
#include <cuda_runtime.h>

// PCEN: B=32, T=4000, C=128, fp32.
//   ema_t = w*x_t + (1-w)*ema_{t-1},  ema_{-1} := x_0  (so ema_0 = x_0)
//   out   = (x/(1e-12+ema)^alpha + delta)^(1/root) - delta^(1/root)
//
// Exact 3-pass segmented scan, S=250 segments of L=16 (8000 warps for
// pass1/pass3 -> ~54 warps/SM requested; R13's 4000 warps left all passes
// latency-starved).

#define B_ 32
#define T_ 4000
#define C_ 128
#define S_ 250
#define L_ (T_ / S_)            // 16
#define FLOOR_ 1e-12f
#define WARPS_TOTAL (B_ * S_)   // 8000
#define TPB_ 256
#define GRID_ (WARPS_TOTAL / (TPB_ / 32))  // 1000 blocks

// scratch (no cudaMalloc allowed): 2 x 4 MiB
__device__ float g_z[B_ * S_ * C_];
__device__ float g_A[B_ * S_ * C_];

__device__ __forceinline__ float clip01(float w) {
    return fminf(fmaxf(w, 0.0f), 1.0f);
}

__device__ __forceinline__ float sqrt_approx(float v) {
    float r;
    asm("sqrt.approx.f32 %0, %1;" : "=f"(r) : "f"(v));
    return r;
}

__device__ __forceinline__ void stcs4(float4* p, float4 v) {
    asm volatile("st.global.cs.v4.f32 [%0], {%1, %2, %3, %4};"
                 :: "l"(p), "f"(v.x), "f"(v.y), "f"(v.z), "f"(v.w) : "memory");
}

// ---------------------------------------------------------------------------
// Pass 1: local segment scans (carry-in = 0).  Front-batched loads: all 16
// float4 loads issued before the FMA reduction -> MLP ~16/thread.
// ---------------------------------------------------------------------------
__global__ __launch_bounds__(TPB_) void pcen_pass1(const float* __restrict__ x,
                                                   const float* __restrict__ ew) {
    const int gw   = (blockIdx.x * blockDim.x + threadIdx.x) >> 5;
    const int lane = threadIdx.x & 31;
    const int b = gw / S_;
    const int s = gw % S_;
    const int c0 = lane * 4;

    const float4 w4 = *reinterpret_cast<const float4*>(ew + c0);
    const float w0 = clip01(w4.x), w1 = clip01(w4.y), w2 = clip01(w4.z), w3 = clip01(w4.w);
    const float o0 = 1.0f - w0, o1 = 1.0f - w1, o2 = 1.0f - w2, o3 = 1.0f - w3;

    const float4* xp =
        reinterpret_cast<const float4*>(x + (b * T_ + s * L_) * C_ + c0);

    float4 xv[L_];
#pragma unroll
    for (int t = 0; t < L_; ++t) xv[t] = xp[t * (C_ / 4)];

    float a0 = 0.0f, a1 = 0.0f, a2 = 0.0f, a3 = 0.0f;
#pragma unroll
    for (int t = 0; t < L_; ++t) {
        a0 = fmaf(o0, a0, w0 * xv[t].x);
        a1 = fmaf(o1, a1, w1 * xv[t].y);
        a2 = fmaf(o2, a2, w2 * xv[t].z);
        a3 = fmaf(o3, a3, w3 * xv[t].w);
    }
    *reinterpret_cast<float4*>(g_z + (b * S_ + s) * C_ + c0) =
        make_float4(a0, a1, a2, a3);
}

// ---------------------------------------------------------------------------
// Pass 2: combine segment carries per (b, c).  4096 threads, 250 steps.
// Loads are independent of the serial carry FMA -> latency mostly hidden.
// ---------------------------------------------------------------------------
__global__ __launch_bounds__(256) void pcen_pass2(const float* __restrict__ x,
                                                  const float* __restrict__ ew) {
    const int gt = blockIdx.x * blockDim.x + threadIdx.x;  // 0..4095
    const int b = gt / C_;
    const int c = gt % C_;
    const float w  = clip01(ew[c]);
    const float om = 1.0f - w;
    // om^16 by repeated squaring (exact, 4 FMULs)
    float d = om * om;   // ^2
    d = d * d;           // ^4
    d = d * d;           // ^8
    d = d * d;           // ^16
    const float decay = d;

    float acc = x[b * T_ * C_ + c];              // ema_{-1} = x[b, 0, c]
#pragma unroll 10
    for (int s = 0; s < S_; ++s) {
        const int idx = (b * S_ + s) * C_ + c;
        g_A[idx] = acc;                          // carry INTO segment s
        acc = fmaf(decay, acc, g_z[idx]);        // carry at end of segment s
    }
}

// ---------------------------------------------------------------------------
// Pass 3: replay with exact carry + pointwise PCEN transform
// ---------------------------------------------------------------------------
__global__ __launch_bounds__(TPB_) void pcen_pass3(const float* __restrict__ x,
                                                   const float* __restrict__ alpha,
                                                   const float* __restrict__ delta,
                                                   const float* __restrict__ root,
                                                   const float* __restrict__ ew,
                                                   float* __restrict__ out) {
    const int gw   = (blockIdx.x * blockDim.x + threadIdx.x) >> 5;
    const int lane = threadIdx.x & 31;
    const int b = gw / S_;
    const int s = gw % S_;
    const int c0 = lane * 4;

    const float4 w4 = *reinterpret_cast<const float4*>(ew + c0);
    const float w0 = clip01(w4.x), w1 = clip01(w4.y), w2 = clip01(w4.z), w3 = clip01(w4.w);
    const float o0 = 1.0f - w0, o1 = 1.0f - w1, o2 = 1.0f - w2, o3 = 1.0f - w3;

    const float4 al4 = *reinterpret_cast<const float4*>(alpha + c0);
    const float na0 = -fminf(al4.x, 1.0f), na1 = -fminf(al4.y, 1.0f);
    const float na2 = -fminf(al4.z, 1.0f), na3 = -fminf(al4.w, 1.0f);

    const float4 de4 = *reinterpret_cast<const float4*>(delta + c0);

    const float4 rt4 = *reinterpret_cast<const float4*>(root + c0);
    const float r0 = 1.0f / fmaxf(rt4.x, 1.0f), r1 = 1.0f / fmaxf(rt4.y, 1.0f);
    const float r2 = 1.0f / fmaxf(rt4.z, 1.0f), r3 = 1.0f / fmaxf(rt4.w, 1.0f);

    const float4 A = *reinterpret_cast<const float4*>(g_A + (b * S_ + s) * C_ + c0);
    float a0 = A.x, a1 = A.y, a2 = A.z, a3 = A.w;

    const int base = (b * T_ + s * L_) * C_ + c0;
    const float4* xp = reinterpret_cast<const float4*>(x + base);
    float4*       op = reinterpret_cast<float4*>(out + base);

    // warp-uniform specialization: all four lanes' roots == 2  ->  sqrt path
    const bool lane_sqrt = (r0 == 0.5f) & (r1 == 0.5f) & (r2 == 0.5f) & (r3 == 0.5f);
    if (__all_sync(0xffffffffu, lane_sqrt)) {
        const float dp0 = sqrt_approx(de4.x), dp1 = sqrt_approx(de4.y);
        const float dp2 = sqrt_approx(de4.z), dp3 = sqrt_approx(de4.w);
#pragma unroll
        for (int t = 0; t < L_; ++t) {
            const float4 xv = xp[t * (C_ / 4)];
            a0 = fmaf(o0, a0, w0 * xv.x);
            a1 = fmaf(o1, a1, w1 * xv.y);
            a2 = fmaf(o2, a2, w2 * xv.z);
            a3 = fmaf(o3, a3, w3 * xv.w);

            const float s0 = __powf(a0 + FLOOR_, na0);
            const float s1 = __powf(a1 + FLOOR_, na1);
            const float s2 = __powf(a2 + FLOOR_, na2);
            const float s3 = __powf(a3 + FLOOR_, na3);

            float4 ov;
            ov.x = sqrt_approx(fmaf(xv.x, s0, de4.x)) - dp0;
            ov.y = sqrt_approx(fmaf(xv.y, s1, de4.y)) - dp1;
            ov.z = sqrt_approx(fmaf(xv.z, s2, de4.z)) - dp2;
            ov.w = sqrt_approx(fmaf(xv.w, s3, de4.w)) - dp3;

            stcs4(op + t * (C_ / 4), ov);
        }
    } else {
        const float dp0 = __powf(de4.x, r0), dp1 = __powf(de4.y, r1);
        const float dp2 = __powf(de4.z, r2), dp3 = __powf(de4.w, r3);
#pragma unroll
        for (int t = 0; t < L_; ++t) {
            const float4 xv = xp[t * (C_ / 4)];
            a0 = fmaf(o0, a0, w0 * xv.x);
            a1 = fmaf(o1, a1, w1 * xv.y);
            a2 = fmaf(o2, a2, w2 * xv.z);
            a3 = fmaf(o3, a3, w3 * xv.w);

            const float s0 = __powf(a0 + FLOOR_, na0);
            const float s1 = __powf(a1 + FLOOR_, na1);
            const float s2 = __powf(a2 + FLOOR_, na2);
            const float s3 = __powf(a3 + FLOOR_, na3);

            const float u0 = fmaf(xv.x, s0, de4.x);
            const float u1 = fmaf(xv.y, s1, de4.y);
            const float u2 = fmaf(xv.z, s2, de4.z);
            const float u3 = fmaf(xv.w, s3, de4.w);

            float4 ov;
            ov.x = __powf(u0, r0) - dp0;
            ov.y = __powf(u1, r1) - dp1;
            ov.z = __powf(u2, r2) - dp2;
            ov.w = __powf(u3, r3) - dp3;

            stcs4(op + t * (C_ / 4), ov);
        }
    }
}

// ---------------------------------------------------------------------------
extern "C" void kernel_launch(void* const* d_in, const int* in_sizes, int n_in,
                              void* d_out, int out_size) {
    const float* x     = (const float*)d_in[0];
    const float* alpha = (const float*)d_in[1];
    const float* delta = (const float*)d_in[2];
    const float* root  = (const float*)d_in[3];
    const float* ew    = (const float*)d_in[4];
    float* out = (float*)d_out;

    pcen_pass1<<<GRID_, TPB_>>>(x, ew);
    pcen_pass2<<<(B_ * C_) / 256, 256>>>(x, ew);
    pcen_pass3<<<GRID_, TPB_>>>(x, alpha, delta, root, ew, out);
}

// round 15
// speedup vs baseline: 2.2239x; 2.2239x over previous
#include <cuda_runtime.h>

// PCEN: B=32, T=4000, C=128, fp32.
//   ema_t = w*x_t + (1-w)*ema_{t-1},  ema_{-1} := x_0  (so ema_0 = x_0)
//   out   = (x/(1e-12+ema)^alpha + delta)^(1/root) - delta^(1/root)
//
// Exact 3-pass segmented scan, S=250 segments of L=16.
// R15 fixes: pass2 batched prefetch (was load-serialized, ~29us);
//            pass3 __stcs intrinsic instead of asm-with-memory-clobber
//            (the clobber serialized every iteration's LDG), + prefetch.

#define B_ 32
#define T_ 4000
#define C_ 128
#define S_ 250
#define L_ (T_ / S_)            // 16
#define FLOOR_ 1e-12f
#define WARPS_TOTAL (B_ * S_)   // 8000
#define TPB_ 256
#define GRID_ (WARPS_TOTAL / (TPB_ / 32))  // 1000 blocks
#define PF_ 10                  // pass2 prefetch depth (250 = 25 * 10)

// scratch (no cudaMalloc allowed): 2 x 4 MiB
__device__ float g_z[B_ * S_ * C_];
__device__ float g_A[B_ * S_ * C_];

__device__ __forceinline__ float clip01(float w) {
    return fminf(fmaxf(w, 0.0f), 1.0f);
}

__device__ __forceinline__ float sqrt_approx(float v) {
    float r;
    asm("sqrt.approx.f32 %0, %1;" : "=f"(r) : "f"(v));
    return r;
}

// ---------------------------------------------------------------------------
// Pass 1: local segment scans (carry-in = 0).  Front-batched loads: all 16
// float4 loads issued before the FMA reduction -> MLP ~16/thread.
// ---------------------------------------------------------------------------
__global__ __launch_bounds__(TPB_) void pcen_pass1(const float* __restrict__ x,
                                                   const float* __restrict__ ew) {
    const int gw   = (blockIdx.x * blockDim.x + threadIdx.x) >> 5;
    const int lane = threadIdx.x & 31;
    const int b = gw / S_;
    const int s = gw % S_;
    const int c0 = lane * 4;

    const float4 w4 = *reinterpret_cast<const float4*>(ew + c0);
    const float w0 = clip01(w4.x), w1 = clip01(w4.y), w2 = clip01(w4.z), w3 = clip01(w4.w);
    const float o0 = 1.0f - w0, o1 = 1.0f - w1, o2 = 1.0f - w2, o3 = 1.0f - w3;

    const float4* xp =
        reinterpret_cast<const float4*>(x + (b * T_ + s * L_) * C_ + c0);

    float4 xv[L_];
#pragma unroll
    for (int t = 0; t < L_; ++t) xv[t] = xp[t * (C_ / 4)];

    float a0 = 0.0f, a1 = 0.0f, a2 = 0.0f, a3 = 0.0f;
#pragma unroll
    for (int t = 0; t < L_; ++t) {
        a0 = fmaf(o0, a0, w0 * xv[t].x);
        a1 = fmaf(o1, a1, w1 * xv[t].y);
        a2 = fmaf(o2, a2, w2 * xv[t].z);
        a3 = fmaf(o3, a3, w3 * xv[t].w);
    }
    *reinterpret_cast<float4*>(g_z + (b * S_ + s) * C_ + c0) =
        make_float4(a0, a1, a2, a3);
}

// ---------------------------------------------------------------------------
// Pass 2: combine segment carries per (b, c).  4096 threads, 250 steps.
// Explicit tile prefetch: 10 independent LDGs in flight per tile, so the
// serial FMA chain (4 cyc/step) is the only dependency, not L2 latency.
// ---------------------------------------------------------------------------
__global__ __launch_bounds__(256) void pcen_pass2(const float* __restrict__ x,
                                                  const float* __restrict__ ew) {
    const int gt = blockIdx.x * blockDim.x + threadIdx.x;  // 0..4095
    const int b = gt / C_;
    const int c = gt % C_;
    const float w  = clip01(ew[c]);
    const float om = 1.0f - w;
    // om^16 by repeated squaring (exact, 4 FMULs)
    float d = om * om;   // ^2
    d = d * d;           // ^4
    d = d * d;           // ^8
    d = d * d;           // ^16
    const float decay = d;

    float acc = x[b * T_ * C_ + c];              // ema_{-1} = x[b, 0, c]
    const int base = b * S_ * C_ + c;
#pragma unroll 1
    for (int tile = 0; tile < S_ / PF_; ++tile) {
        float z[PF_];
#pragma unroll
        for (int k = 0; k < PF_; ++k)
            z[k] = g_z[base + (tile * PF_ + k) * C_];
#pragma unroll
        for (int k = 0; k < PF_; ++k) {
            g_A[base + (tile * PF_ + k) * C_] = acc;  // carry INTO segment
            acc = fmaf(decay, acc, z[k]);             // carry out
        }
    }
}

// ---------------------------------------------------------------------------
// Pass 3: replay with exact carry + pointwise PCEN transform
// ---------------------------------------------------------------------------
__global__ __launch_bounds__(TPB_) void pcen_pass3(const float* __restrict__ x,
                                                   const float* __restrict__ alpha,
                                                   const float* __restrict__ delta,
                                                   const float* __restrict__ root,
                                                   const float* __restrict__ ew,
                                                   float* __restrict__ out) {
    const int gw   = (blockIdx.x * blockDim.x + threadIdx.x) >> 5;
    const int lane = threadIdx.x & 31;
    const int b = gw / S_;
    const int s = gw % S_;
    const int c0 = lane * 4;

    const float4 w4 = *reinterpret_cast<const float4*>(ew + c0);
    const float w0 = clip01(w4.x), w1 = clip01(w4.y), w2 = clip01(w4.z), w3 = clip01(w4.w);
    const float o0 = 1.0f - w0, o1 = 1.0f - w1, o2 = 1.0f - w2, o3 = 1.0f - w3;

    const float4 al4 = *reinterpret_cast<const float4*>(alpha + c0);
    const float na0 = -fminf(al4.x, 1.0f), na1 = -fminf(al4.y, 1.0f);
    const float na2 = -fminf(al4.z, 1.0f), na3 = -fminf(al4.w, 1.0f);

    const float4 de4 = *reinterpret_cast<const float4*>(delta + c0);

    const float4 rt4 = *reinterpret_cast<const float4*>(root + c0);
    const float r0 = 1.0f / fmaxf(rt4.x, 1.0f), r1 = 1.0f / fmaxf(rt4.y, 1.0f);
    const float r2 = 1.0f / fmaxf(rt4.z, 1.0f), r3 = 1.0f / fmaxf(rt4.w, 1.0f);

    const float4 A = *reinterpret_cast<const float4*>(g_A + (b * S_ + s) * C_ + c0);
    float a0 = A.x, a1 = A.y, a2 = A.z, a3 = A.w;

    const int base = (b * T_ + s * L_) * C_ + c0;
    const float4* xp = reinterpret_cast<const float4*>(x + base);
    float4*       op = reinterpret_cast<float4*>(out + base);

    // warp-uniform specialization: all four lanes' roots == 2  ->  sqrt path
    const bool lane_sqrt = (r0 == 0.5f) & (r1 == 0.5f) & (r2 == 0.5f) & (r3 == 0.5f);
    if (__all_sync(0xffffffffu, lane_sqrt)) {
        const float dp0 = sqrt_approx(de4.x), dp1 = sqrt_approx(de4.y);
        const float dp2 = sqrt_approx(de4.z), dp3 = sqrt_approx(de4.w);
        float4 xv = xp[0];
#pragma unroll
        for (int t = 0; t < L_; ++t) {
            const float4 xn = (t + 1 < L_) ? xp[(t + 1) * (C_ / 4)]
                                           : make_float4(0.f, 0.f, 0.f, 0.f);
            a0 = fmaf(o0, a0, w0 * xv.x);
            a1 = fmaf(o1, a1, w1 * xv.y);
            a2 = fmaf(o2, a2, w2 * xv.z);
            a3 = fmaf(o3, a3, w3 * xv.w);

            const float s0 = __powf(a0 + FLOOR_, na0);
            const float s1 = __powf(a1 + FLOOR_, na1);
            const float s2 = __powf(a2 + FLOOR_, na2);
            const float s3 = __powf(a3 + FLOOR_, na3);

            float4 ov;
            ov.x = sqrt_approx(fmaf(xv.x, s0, de4.x)) - dp0;
            ov.y = sqrt_approx(fmaf(xv.y, s1, de4.y)) - dp1;
            ov.z = sqrt_approx(fmaf(xv.z, s2, de4.z)) - dp2;
            ov.w = sqrt_approx(fmaf(xv.w, s3, de4.w)) - dp3;

            __stcs(op + t * (C_ / 4), ov);
            xv = xn;
        }
    } else {
        const float dp0 = __powf(de4.x, r0), dp1 = __powf(de4.y, r1);
        const float dp2 = __powf(de4.z, r2), dp3 = __powf(de4.w, r3);
        float4 xv = xp[0];
#pragma unroll
        for (int t = 0; t < L_; ++t) {
            const float4 xn = (t + 1 < L_) ? xp[(t + 1) * (C_ / 4)]
                                           : make_float4(0.f, 0.f, 0.f, 0.f);
            a0 = fmaf(o0, a0, w0 * xv.x);
            a1 = fmaf(o1, a1, w1 * xv.y);
            a2 = fmaf(o2, a2, w2 * xv.z);
            a3 = fmaf(o3, a3, w3 * xv.w);

            const float s0 = __powf(a0 + FLOOR_, na0);
            const float s1 = __powf(a1 + FLOOR_, na1);
            const float s2 = __powf(a2 + FLOOR_, na2);
            const float s3 = __powf(a3 + FLOOR_, na3);

            const float u0 = fmaf(xv.x, s0, de4.x);
            const float u1 = fmaf(xv.y, s1, de4.y);
            const float u2 = fmaf(xv.z, s2, de4.z);
            const float u3 = fmaf(xv.w, s3, de4.w);

            float4 ov;
            ov.x = __powf(u0, r0) - dp0;
            ov.y = __powf(u1, r1) - dp1;
            ov.z = __powf(u2, r2) - dp2;
            ov.w = __powf(u3, r3) - dp3;

            __stcs(op + t * (C_ / 4), ov);
            xv = xn;
        }
    }
}

// ---------------------------------------------------------------------------
extern "C" void kernel_launch(void* const* d_in, const int* in_sizes, int n_in,
                              void* d_out, int out_size) {
    const float* x     = (const float*)d_in[0];
    const float* alpha = (const float*)d_in[1];
    const float* delta = (const float*)d_in[2];
    const float* root  = (const float*)d_in[3];
    const float* ew    = (const float*)d_in[4];
    float* out = (float*)d_out;

    pcen_pass1<<<GRID_, TPB_>>>(x, ew);
    pcen_pass2<<<(B_ * C_) / 256, 256>>>(x, ew);
    pcen_pass3<<<GRID_, TPB_>>>(x, alpha, delta, root, ew, out);
}